// round 1
// baseline (speedup 1.0000x reference)
#include <cuda_runtime.h>
#include <cuda_bf16.h>
#include <math.h>

// Problem constants (max_depth = 8)
#define BATCH 512
#define FEAT  512
#define NS    255   // n_splits = 2^8 - 1
#define NN    511   // n_nodes  = 2^9 - 1
#define NCAND 21

// -------- scratch (device globals; no allocation allowed) --------
__device__ float g_qsplit[BATCH * NS];
__device__ float g_qnode[BATCH * NN];
__device__ float g_ga[NN * NCAND];
__device__ float g_anode[NN];

// ================= K1: q_split = x @ W + b  (512x255, K=512) =================
#define BM 32
#define BN 32
#define BK 32
__global__ void k_gemm(const float* __restrict__ x, const float* __restrict__ W,
                       const float* __restrict__ bias) {
    __shared__ float xs[BM][BK + 1];
    __shared__ float ws[BK][BN + 1];
    int tid = threadIdx.x;          // 256 threads
    int tx = tid & 31;              // col within tile
    int ty = tid >> 5;              // 0..7
    int b0 = blockIdx.y * BM;
    int s0 = blockIdx.x * BN;
    float acc[4] = {0.f, 0.f, 0.f, 0.f};
    for (int k0 = 0; k0 < FEAT; k0 += BK) {
#pragma unroll
        for (int i = 0; i < 4; i++) {
            int r = ty + 8 * i;
            xs[r][tx] = x[(b0 + r) * FEAT + k0 + tx];
            int s = s0 + tx;
            ws[r][tx] = (s < NS) ? W[(k0 + r) * NS + s] : 0.f;
        }
        __syncthreads();
#pragma unroll
        for (int kk = 0; kk < BK; kk++) {
            float wv = ws[kk][tx];
            acc[0] += xs[ty][kk] * wv;
            acc[1] += xs[ty + 8][kk] * wv;
            acc[2] += xs[ty + 16][kk] * wv;
            acc[3] += xs[ty + 24][kk] * wv;
        }
        __syncthreads();
    }
    int s = s0 + tx;
    if (s < NS) {
        float bv = bias[s];
#pragma unroll
        for (int i = 0; i < 4; i++)
            g_qsplit[(b0 + ty + 8 * i) * NS + s] = acc[i] + bv;
    }
}

// ======== K2: q_node[b,n] = min(1, min over ancestors of signed q_split) ========
__global__ void k_qnode() {
    __shared__ float sq[NS];
    int b = blockIdx.x;
    int tid = threadIdx.x;   // 512
    if (tid < NS) sq[tid] = g_qsplit[b * NS + tid];
    __syncthreads();
    if (tid < NN) {
        float m = 1.0f;
        int a = tid;
        while (a > 0) {
            int p = (a - 1) >> 1;
            float q = sq[p];
            if (a == 2 * p + 1) q = -q;   // left-child edge: M = -1
            m = fminf(m, q);
            a = p;
        }
        g_qnode[b * NN + tid] = m;
    }
}

// ===== K3: g_a[n,j] = 0.5 a_j^2 + 0.5 * sum_b [a_j <= q+0.5] (a_j-(q+0.5))^2 =====
__global__ void k_ga() {
    int n = blockIdx.x;        // 511 blocks
    int tid = threadIdx.x;     // 512 threads, one per batch element
    float th = g_qnode[tid * NN + n] + 0.5f;
    float acc[NCAND];
#pragma unroll
    for (int j = 0; j < NCAND; j++) {
        float aj = (float)j / 20.0f;
        float d = aj - th;
        acc[j] = (aj <= th) ? d * d : 0.f;
    }
#pragma unroll
    for (int j = 0; j < NCAND; j++)
        for (int off = 16; off; off >>= 1)
            acc[j] += __shfl_down_sync(0xffffffffu, acc[j], off);
    __shared__ float part[16][NCAND];
    int lane = tid & 31, w = tid >> 5;
    if (lane == 0)
        for (int j = 0; j < NCAND; j++) part[w][j] = acc[j];
    __syncthreads();
    if (tid < NCAND) {
        float s = 0.f;
        for (int w2 = 0; w2 < 16; w2++) s += part[w2][tid];
        float aj = (float)tid / 20.0f;
        g_ga[n * NCAND + tid] = 0.5f * aj * aj + 0.5f * s;
    }
}

// ============================ K4: sequential scan ============================
// n2g row i only ever has support {i, parent(i)} with coefs (ct[i], cp[i]);
// n2g column g only ever has support {g, 2g+1, 2g+2}.
__device__ __forceinline__ float warp_softmin(int g, const float* sct, const float* scp) {
    const unsigned F = 0xffffffffu;
    int lane = threadIdx.x & 31;
    float l = -1e30f;
    if (lane < NCAND) {
        float gg = sct[g] * g_ga[g * NCAND + lane];
        int L = 2 * g + 1, R = 2 * g + 2;
        if (L < NN) gg += scp[L] * g_ga[L * NCAND + lane];
        if (R < NN) gg += scp[R] * g_ga[R * NCAND + lane];
        l = -100.0f * gg;                // -SOFTMIN_TEMP * g_grp
    }
    float m = l;
#pragma unroll
    for (int off = 16; off; off >>= 1) m = fmaxf(m, __shfl_xor_sync(F, m, off));
    float e = (lane < NCAND) ? expf(l - m) : 0.f;
    float S = e;
#pragma unroll
    for (int off = 16; off; off >>= 1) S += __shfl_xor_sync(F, S, off);
    float w = e / S;
    float c = (lane < NCAND) ? ((float)lane / 20.0f) * w : 0.f;
    float A = c;
#pragma unroll
    for (int off = 16; off; off >>= 1) A += __shfl_xor_sync(F, A, off);
    return A;
}

__global__ void k_scan() {
    __shared__ float sa[NN];    // a_grp
    __shared__ float san[NN];   // a_node
    __shared__ float sct[NN];   // row-i coef at col i
    __shared__ float scp[NN];   // row-i coef at col parent(i)
    __shared__ float rv[16];
    __shared__ int ri[16];
    __shared__ int s_t, s_stop;
    int tid = threadIdx.x;       // 512
    int lane = tid & 31, wp = tid >> 5;
    if (tid < NN) { sct[tid] = 1.f; scp[tid] = 0.f; }
    if (tid == 0) s_stop = 0;
    __syncthreads();
    // initial a_grp for all 511 groups (16 warps, strided)
    for (int g = wp; g < NN; g += 16) {
        float A = warp_softmin(g, sct, scp);
        if (lane == 0) sa[g] = A;
    }
    __syncthreads();
    for (int it = 0; it < NN + 1; ++it) {
        if (tid < NN) {
            float an;
            if (tid == 0) an = sa[0];
            else an = scp[tid] * sa[(tid - 1) >> 1] + sct[tid] * sa[tid];
            san[tid] = an;
        }
        __syncthreads();
        // viol + argmax (first-index tie rule)
        float v = -1e30f; int idx = 1 << 30;
        if (tid < NN) {
            v = (tid == 0) ? san[0] - 1.f : san[tid] - san[(tid - 1) >> 1];
            idx = tid;
        }
#pragma unroll
        for (int off = 16; off; off >>= 1) {
            float ov = __shfl_down_sync(0xffffffffu, v, off);
            int oi = __shfl_down_sync(0xffffffffu, idx, off);
            if (ov > v || (ov == v && oi < idx)) { v = ov; idx = oi; }
        }
        if (lane == 0) { rv[wp] = v; ri[wp] = idx; }
        __syncthreads();
        if (tid == 0) {
            float bv = rv[0]; int bi = ri[0];
            for (int w2 = 1; w2 < 16; w2++)
                if (rv[w2] > bv || (rv[w2] == bv && ri[w2] < bi)) { bv = rv[w2]; bi = ri[w2]; }
            if (bv <= 1e-8f && bi > 0 && it < NN) {
                s_t = bi;
                sct[bi] -= 1.f;      // merge node bi toward its parent
                scp[bi] += 1.f;
            } else {
                s_stop = 1;          // fixed point: remaining iterations are no-ops
            }
        }
        __syncthreads();
        if (s_stop) break;
        // only columns t and parent(t) changed -> recompute their softmins
        if (tid < 64) {
            int t = s_t;
            int g = (wp == 0) ? t : ((t - 1) >> 1);
            float A = warp_softmin(g, sct, scp);
            if (lane == 0) sa[g] = A;
        }
        __syncthreads();
    }
    if (tid < NN) g_anode[tid] = san[tid];
}

// ================= K5: out[b,n] = clip(q_node[b,n], 0, a_node[n]) =================
__global__ void k_clip(float* __restrict__ out) {
    int i = blockIdx.x * blockDim.x + threadIdx.x;
    if (i < BATCH * NN) {
        int n = i % NN;
        float a = __ldg(&g_anode[n]);
        float q = g_qnode[i];
        out[i] = fminf(fmaxf(q, 0.f), a);
    }
}

extern "C" void kernel_launch(void* const* d_in, const int* in_sizes, int n_in,
                              void* d_out, int out_size) {
    const float* x = (const float*)d_in[0];   // (512, 512)
    const float* W = (const float*)d_in[1];   // (512, 255)
    const float* b = (const float*)d_in[2];   // (255,)
    float* out = (float*)d_out;               // (512, 511)

    k_gemm<<<dim3(8, 16), 256>>>(x, W, b);
    k_qnode<<<BATCH, 512>>>();
    k_ga<<<NN, 512>>>();
    k_scan<<<1, 512>>>();
    k_clip<<<(BATCH * NN + 255) / 256, 256>>>(out);
}

// round 4
// speedup vs baseline: 1.4605x; 1.4605x over previous
#include <cuda_runtime.h>
#include <math.h>

#define BATCH 512
#define FEAT  512
#define NS    255
#define NN    511
#define NCAND 21

__device__ float g_qsplit[BATCH * NS];
__device__ float g_qnode[BATCH * NN];
__device__ float g_qnodeT[NN * BATCH];
__device__ float g_ga[NN * NCAND];
__device__ float g_sa0[NN];
__device__ float g_anode[NN];

// ================= K1: q_split = x @ W + b  (2x2 register micro-tile) =================
__global__ void k_gemm(const float* __restrict__ x, const float* __restrict__ W,
                       const float* __restrict__ bias) {
    __shared__ float xsT[32][33];   // [k][m]
    __shared__ float ws[32][34];    // [k][n]
    int tid = threadIdx.x;          // 256
    int tx = tid & 15;              // n-pair
    int ty = tid >> 4;              // m-pair
    int b0 = blockIdx.y * 32;
    int s0 = blockIdx.x * 32;
    int lc = tid & 31;
    int lr = tid >> 5;
    float a00 = 0.f, a01 = 0.f, a10 = 0.f, a11 = 0.f;
    for (int k0 = 0; k0 < FEAT; k0 += 32) {
#pragma unroll
        for (int i = 0; i < 4; i++) {
            int r = lr + 8 * i;
            xsT[lc][r] = x[(b0 + r) * FEAT + k0 + lc];
            int s = s0 + lc;
            ws[r][lc] = (s < NS) ? W[(k0 + r) * NS + s] : 0.f;
        }
        __syncthreads();
#pragma unroll
        for (int kk = 0; kk < 32; kk++) {
            float xa = xsT[kk][2 * ty], xb = xsT[kk][2 * ty + 1];
            float wa = ws[kk][2 * tx], wb = ws[kk][2 * tx + 1];
            a00 += xa * wa; a01 += xa * wb;
            a10 += xb * wa; a11 += xb * wb;
        }
        __syncthreads();
    }
    int s = s0 + 2 * tx;
    int r0 = b0 + 2 * ty, r1 = r0 + 1;
    if (s < NS) {
        float bv = bias[s];
        g_qsplit[r0 * NS + s] = a00 + bv;
        g_qsplit[r1 * NS + s] = a10 + bv;
    }
    if (s + 1 < NS) {
        float bv = bias[s + 1];
        g_qsplit[r0 * NS + s + 1] = a01 + bv;
        g_qsplit[r1 * NS + s + 1] = a11 + bv;
    }
}

// ======== K2: q_node = min(1, min over ancestors of signed q_split); dual layout ========
__global__ void k_qnode() {
    __shared__ float sq[NS];
    int b = blockIdx.x;
    int tid = threadIdx.x;   // 512
    if (tid < NS) sq[tid] = g_qsplit[b * NS + tid];
    __syncthreads();
    if (tid < NN) {
        float m = 1.0f;
        int a = tid;
        while (a > 0) {
            int p = (a - 1) >> 1;
            float q = sq[p];
            if (a == 2 * p + 1) q = -q;
            m = fminf(m, q);
            a = p;
        }
        g_qnode[b * NN + tid] = m;
        g_qnodeT[tid * BATCH + b] = m;   // scattered store (no stall), coalesced read later
    }
}

// ===== K3: g_a + initial softmin (n2g = eye => g_grp = ga exactly) =====
__global__ void k_ga() {
    int n = blockIdx.x;        // 511 blocks
    int tid = threadIdx.x;     // 512 threads
    float th = g_qnodeT[n * BATCH + tid] + 0.5f;   // coalesced
    float acc[NCAND];
#pragma unroll
    for (int j = 0; j < NCAND; j++) {
        float aj = (float)j / 20.0f;
        float d = aj - th;
        acc[j] = (aj <= th) ? d * d : 0.f;
    }
#pragma unroll
    for (int j = 0; j < NCAND; j++)
        for (int off = 16; off; off >>= 1)
            acc[j] += __shfl_down_sync(0xffffffffu, acc[j], off);
    __shared__ float part[16][NCAND];
    int lane = tid & 31, w = tid >> 5;
    if (lane == 0)
        for (int j = 0; j < NCAND; j++) part[w][j] = acc[j];
    __syncthreads();
    if (tid < 32) {
        const unsigned F = 0xffffffffu;
        float l = __int_as_float(0xff800000);
        if (tid < NCAND) {
            float s = 0.f;
            for (int w2 = 0; w2 < 16; w2++) s += part[w2][tid];
            float aj = (float)tid / 20.0f;
            float v = 0.5f * aj * aj + 0.5f * s;
            g_ga[n * NCAND + tid] = v;
            l = -100.0f * v;
        }
        // 21-lane softmin (same structure as R1's passing warp_softmin)
        float m = l;
#pragma unroll
        for (int off = 16; off; off >>= 1) m = fmaxf(m, __shfl_xor_sync(F, m, off));
        float e = (tid < NCAND) ? expf(l - m) : 0.f;
        float S = e;
#pragma unroll
        for (int off = 16; off; off >>= 1) S += __shfl_xor_sync(F, S, off);
        float ww = e / S;
        float c = (tid < NCAND) ? ((float)tid / 20.0f) * ww : 0.f;
        float A = c;
#pragma unroll
        for (int off = 16; off; off >>= 1) A += __shfl_xor_sync(F, A, off);
        if (tid == 0) g_sa0[n] = A;
    }
}

// ============================ K4: single-warp sequential scan ============================
__global__ void __launch_bounds__(512) k_scan() {
    __shared__ float sa[NN];
    __shared__ float san[NN];
    __shared__ __align__(16) float viol[NN + 1];
    __shared__ float sct[NN];
    __shared__ float scp[NN];
    int tid = threadIdx.x;    // 512
    const unsigned F = 0xffffffffu;
    const float NEG_INF = __int_as_float(0xff800000);

    // prologue: init state + warm L1 with ga
    if (tid < NN) {
        sct[tid] = 1.f; scp[tid] = 0.f;
        float a = g_sa0[tid];
        sa[tid] = a;
        san[tid] = a;          // a_node_0 = a_grp (eye)  [bit-exact]
    }
    if (tid == NN) viol[NN] = NEG_INF;
    float warm = 0.f;
    for (int i = tid; i < NN * NCAND; i += 512) warm += __ldg(&g_ga[i]);
    if (warm == -12345.6789f) g_anode[0] = warm;   // never true; keeps the warm loads
    __syncthreads();
    if (tid < NN) viol[tid] = tid ? san[tid] - san[(tid - 1) >> 1] : san[0] - 1.f;
    __syncthreads();
    if (tid >= 32) return;

    int lane = tid;
    for (int it = 0; it < NN; ++it) {
        // ---- argmax over viol[0..510] (first-index tie), blocked 16/lane ----
        unsigned bkey = 0x007FFFFFu;       // key(-inf)
        int bidx = 1 << 30;
        float bval = NEG_INF;
        const float4* vp = (const float4*)&viol[lane * 16];
#pragma unroll
        for (int q = 0; q < 4; q++) {
            float4 f4 = vp[q];
            float vv0 = f4.x, vv1 = f4.y, vv2 = f4.z, vv3 = f4.w;
#pragma unroll
            for (int c = 0; c < 4; c++) {
                float v = (c == 0) ? vv0 : (c == 1) ? vv1 : (c == 2) ? vv2 : vv3;
                unsigned u = __float_as_uint(v);
                unsigned key = u ^ ((unsigned)((int)u >> 31) | 0x80000000u);
                if (key > bkey) { bkey = key; bidx = lane * 16 + q * 4 + c; bval = v; }
            }
        }
        unsigned mk = __reduce_max_sync(F, bkey);
        unsigned bal = __ballot_sync(F, bkey == mk);
        int src = __ffs(bal) - 1;
        int t = __shfl_sync(F, bidx, src);
        float bv = __shfl_sync(F, bval, src);
        if (!(bv <= 1e-8f) || t == 0) break;   // fixed point -> output frozen

        int p = (t - 1) >> 1;
        if (lane == 0) { sct[t] -= 1.f; scp[t] += 1.f; }
        __syncwarp();

        // ---- both softmins in one warp: lanes 0-6 -> group t, lanes 8-14 -> group p ----
        int g  = (lane < 8) ? t : p;
        int cl = lane & 7;
        bool act = (cl < 7) && (lane < 16);
        float l0 = NEG_INF, l1 = NEG_INF, l2 = NEG_INF;
        int j0 = cl * 3;
        if (act) {
            int L = 2 * g + 1, R = 2 * g + 2;
            float ct = sct[g];
            float cL = (L < NN) ? scp[L] : 0.f;
            float cR = (R < NN) ? scp[R] : 0.f;
            const float* gaG = &g_ga[g * NCAND];
            const float* gaL = (L < NN) ? &g_ga[L * NCAND] : gaG;
            const float* gaR = (R < NN) ? &g_ga[R * NCAND] : gaG;
            float g0 = ct * __ldg(&gaG[j0])     + cL * __ldg(&gaL[j0])     + cR * __ldg(&gaR[j0]);
            float g1 = ct * __ldg(&gaG[j0 + 1]) + cL * __ldg(&gaL[j0 + 1]) + cR * __ldg(&gaR[j0 + 1]);
            float g2 = ct * __ldg(&gaG[j0 + 2]) + cL * __ldg(&gaL[j0 + 2]) + cR * __ldg(&gaR[j0 + 2]);
            l0 = -100.0f * g0; l1 = -100.0f * g1; l2 = -100.0f * g2;
        }
        float m = fmaxf(l0, fmaxf(l1, l2));
        m = fmaxf(m, __shfl_xor_sync(F, m, 1));
        m = fmaxf(m, __shfl_xor_sync(F, m, 2));
        m = fmaxf(m, __shfl_xor_sync(F, m, 4));
        float e0 = act ? expf(l0 - m) : 0.f;
        float e1 = act ? expf(l1 - m) : 0.f;
        float e2 = act ? expf(l2 - m) : 0.f;
        float S = e0 + e1 + e2;
        S += __shfl_xor_sync(F, S, 1);
        S += __shfl_xor_sync(F, S, 2);
        S += __shfl_xor_sync(F, S, 4);
        float w0 = e0 / S, w1 = e1 / S, w2 = e2 / S;     // per-candidate div (matches ref softmax)
        float C = ((float)j0 / 20.0f) * w0
                + ((float)(j0 + 1) / 20.0f) * w1
                + ((float)(j0 + 2) / 20.0f) * w2;
        C += __shfl_xor_sync(F, C, 1);
        C += __shfl_xor_sync(F, C, 2);
        C += __shfl_xor_sync(F, C, 4);
        if (lane == 0) sa[t] = C;
        if (lane == 8) sa[p] = C;
        __syncwarp();

        // ---- incremental a_node updates: {p, sib, t, 2t+1, 2t+2} ----
        int sib = 4 * p + 3 - t;
        if (lane < 5) {
            int i = (lane == 0) ? p : (lane == 1) ? sib : (lane == 2) ? t
                  : (lane == 3) ? 2 * t + 1 : 2 * t + 2;
            if (i < NN)
                san[i] = i ? scp[i] * sa[(i - 1) >> 1] + sct[i] * sa[i] : sa[0];
        }
        __syncwarp();
        // ---- incremental viol updates: changed set ∪ its children (<= 11) ----
        if (lane < 11) {
            int i;
            switch (lane) {
                case 0:  i = p;           break;
                case 1:  i = t;           break;
                case 2:  i = sib;         break;
                case 3:  i = 2 * t + 1;   break;
                case 4:  i = 2 * t + 2;   break;
                case 5:  i = 2 * sib + 1; break;
                case 6:  i = 2 * sib + 2; break;
                case 7:  i = 4 * t + 3;   break;
                case 8:  i = 4 * t + 4;   break;
                case 9:  i = 4 * t + 5;   break;
                default: i = 4 * t + 6;   break;
            }
            if (i < NN)
                viol[i] = i ? san[i] - san[(i - 1) >> 1] : san[0] - 1.f;
        }
        __syncwarp();
    }
    for (int i = lane; i < NN; i += 32) g_anode[i] = san[i];
}

// ================= K5: out = clip(q_node, 0, a_node) =================
__global__ void k_clip(float* __restrict__ out) {
    int i = blockIdx.x * blockDim.x + threadIdx.x;
    if (i < BATCH * NN) {
        int n = i % NN;
        float a = __ldg(&g_anode[n]);
        float q = g_qnode[i];
        out[i] = fminf(fmaxf(q, 0.f), a);
    }
}

extern "C" void kernel_launch(void* const* d_in, const int* in_sizes, int n_in,
                              void* d_out, int out_size) {
    const float* x = (const float*)d_in[0];
    const float* W = (const float*)d_in[1];
    const float* b = (const float*)d_in[2];
    float* out = (float*)d_out;

    k_gemm<<<dim3(8, 16), 256>>>(x, W, b);
    k_qnode<<<BATCH, 512>>>();
    k_ga<<<NN, 512>>>();
    k_scan<<<1, 512>>>();
    k_clip<<<(BATCH * NN + 255) / 256, 256>>>(out);
}

// round 5
// speedup vs baseline: 2.0889x; 1.4303x over previous
#include <cuda_runtime.h>
#include <math.h>

#define BATCH 512
#define FEAT  512
#define NS    255
#define NN    511
#define NCAND 21

__device__ float g_qsplitT[NS * BATCH];   // [s][b]
__device__ float g_qnode[BATCH * NN];     // [b][n] (for clip)
__device__ float g_ga[NN * NCAND];
__device__ float g_sa0[NN];
__device__ float g_anode[NN];

// ========== K1: q_splitT[s][b] = (x @ W + b)[b][s]  (2x2 micro, float2 LDS) ==========
__global__ void k_gemm(const float* __restrict__ x, const float* __restrict__ W,
                       const float* __restrict__ bias) {
    __shared__ float xsT[32][34];   // [k][m], padded for float2
    __shared__ float ws[32][34];    // [k][n]
    int tid = threadIdx.x;          // 256
    int tx = tid & 15;              // m-pair
    int ty = tid >> 4;              // n-pair
    int b0 = blockIdx.y * 32;
    int s0 = blockIdx.x * 32;
    int lc = tid & 31;
    int lr = tid >> 5;
    float a00 = 0.f, a01 = 0.f, a10 = 0.f, a11 = 0.f;
    for (int k0 = 0; k0 < FEAT; k0 += 32) {
#pragma unroll
        for (int i = 0; i < 4; i++) {
            int r = lr + 8 * i;
            xsT[lc][r] = x[(b0 + r) * FEAT + k0 + lc];
            int s = s0 + lc;
            ws[r][lc] = (s < NS) ? W[(k0 + r) * NS + s] : 0.f;
        }
        __syncthreads();
#pragma unroll
        for (int kk = 0; kk < 32; kk++) {
            float2 xv = *(const float2*)&xsT[kk][2 * tx];
            float2 wv = *(const float2*)&ws[kk][2 * ty];
            a00 += xv.x * wv.x; a01 += xv.x * wv.y;
            a10 += xv.y * wv.x; a11 += xv.y * wv.y;
        }
        __syncthreads();
    }
    int s = s0 + 2 * ty;
    int r0 = b0 + 2 * tx, r1 = r0 + 1;
    {   // s <= 254 always valid here
        float bv = bias[s];
        g_qsplitT[s * BATCH + r0] = a00 + bv;
        g_qsplitT[s * BATCH + r1] = a10 + bv;
    }
    if (s + 1 < NS) {
        float bv = bias[s + 1];
        g_qsplitT[(s + 1) * BATCH + r0] = a01 + bv;
        g_qsplitT[(s + 1) * BATCH + r1] = a11 + bv;
    }
}

// ===== K2: fused q_node (ancestor min) + g_a + initial softmin. Block n, 128 thr. =====
__global__ void __launch_bounds__(128) k_ga() {
    int n = blockIdx.x;        // 0..510
    int tid = threadIdx.x;     // 0..127
    float acc[NCAND];
#pragma unroll
    for (int j = 0; j < NCAND; j++) acc[j] = 0.f;

    // ancestor split chain of n (same for all threads — uniform)
    int anc[9]; float sgn[9]; int na = 0;
    {
        int a = n;
        while (a > 0) {
            int p = (a - 1) >> 1;
            anc[na] = p;
            sgn[na] = (a == 2 * p + 1) ? -1.f : 1.f;
            na++;
            a = p;
        }
    }
#pragma unroll 4
    for (int e = 0; e < 4; e++) {
        int b = tid + 128 * e;
        float m = 1.0f;
        for (int k = 0; k < na; k++) {
            float q = g_qsplitT[anc[k] * BATCH + b];   // coalesced
            m = fminf(m, sgn[k] * q);
        }
        g_qnode[b * NN + n] = m;                       // scattered store (no stall)
        float th = m + 0.5f;
#pragma unroll
        for (int j = 0; j < NCAND; j++) {
            float aj = (float)j / 20.0f;
            float d = aj - th;
            acc[j] += (aj <= th) ? d * d : 0.f;
        }
    }
#pragma unroll
    for (int j = 0; j < NCAND; j++)
        for (int off = 16; off; off >>= 1)
            acc[j] += __shfl_down_sync(0xffffffffu, acc[j], off);
    __shared__ float part[4][NCAND];
    int lane = tid & 31, w = tid >> 5;
    if (lane == 0)
        for (int j = 0; j < NCAND; j++) part[w][j] = acc[j];
    __syncthreads();
    if (tid < 32) {
        const unsigned F = 0xffffffffu;
        float l = __int_as_float(0xff800000);
        if (tid < NCAND) {
            float s = part[0][tid] + part[1][tid] + part[2][tid] + part[3][tid];
            float aj = (float)tid / 20.0f;
            float v = 0.5f * aj * aj + 0.5f * s;
            g_ga[n * NCAND + tid] = v;
            l = -100.0f * v;
        }
        float m = l;
#pragma unroll
        for (int off = 16; off; off >>= 1) m = fmaxf(m, __shfl_xor_sync(F, m, off));
        float e = (tid < NCAND) ? expf(l - m) : 0.f;
        float S = e;
#pragma unroll
        for (int off = 16; off; off >>= 1) S += __shfl_xor_sync(F, S, off);
        float ww = e / S;
        float c = (tid < NCAND) ? ((float)tid / 20.0f) * ww : 0.f;
        float A = c;
#pragma unroll
        for (int off = 16; off; off >>= 1) A += __shfl_xor_sync(F, A, off);
        if (tid == 0) g_sa0[n] = A;
    }
}

// ============================ K3: single-warp sequential scan (unchanged) ============================
__global__ void __launch_bounds__(512) k_scan() {
    __shared__ float sa[NN];
    __shared__ float san[NN];
    __shared__ __align__(16) float viol[NN + 1];
    __shared__ float sct[NN];
    __shared__ float scp[NN];
    int tid = threadIdx.x;    // 512
    const unsigned F = 0xffffffffu;
    const float NEG_INF = __int_as_float(0xff800000);

    if (tid < NN) {
        sct[tid] = 1.f; scp[tid] = 0.f;
        float a = g_sa0[tid];
        sa[tid] = a;
        san[tid] = a;
    }
    if (tid == NN) viol[NN] = NEG_INF;
    float warm = 0.f;
    for (int i = tid; i < NN * NCAND; i += 512) warm += __ldg(&g_ga[i]);
    if (warm == -12345.6789f) g_anode[0] = warm;
    __syncthreads();
    if (tid < NN) viol[tid] = tid ? san[tid] - san[(tid - 1) >> 1] : san[0] - 1.f;
    __syncthreads();
    if (tid >= 32) return;

    int lane = tid;
    for (int it = 0; it < NN; ++it) {
        unsigned bkey = 0x007FFFFFu;
        int bidx = 1 << 30;
        float bval = NEG_INF;
        const float4* vp = (const float4*)&viol[lane * 16];
#pragma unroll
        for (int q = 0; q < 4; q++) {
            float4 f4 = vp[q];
            float vv0 = f4.x, vv1 = f4.y, vv2 = f4.z, vv3 = f4.w;
#pragma unroll
            for (int c = 0; c < 4; c++) {
                float v = (c == 0) ? vv0 : (c == 1) ? vv1 : (c == 2) ? vv2 : vv3;
                unsigned u = __float_as_uint(v);
                unsigned key = u ^ ((unsigned)((int)u >> 31) | 0x80000000u);
                if (key > bkey) { bkey = key; bidx = lane * 16 + q * 4 + c; bval = v; }
            }
        }
        unsigned mk = __reduce_max_sync(F, bkey);
        unsigned bal = __ballot_sync(F, bkey == mk);
        int src = __ffs(bal) - 1;
        int t = __shfl_sync(F, bidx, src);
        float bv = __shfl_sync(F, bval, src);
        if (!(bv <= 1e-8f) || t == 0) break;

        int p = (t - 1) >> 1;
        if (lane == 0) { sct[t] -= 1.f; scp[t] += 1.f; }
        __syncwarp();

        int g  = (lane < 8) ? t : p;
        int cl = lane & 7;
        bool act = (cl < 7) && (lane < 16);
        float l0 = NEG_INF, l1 = NEG_INF, l2 = NEG_INF;
        int j0 = cl * 3;
        if (act) {
            int L = 2 * g + 1, R = 2 * g + 2;
            float ct = sct[g];
            float cL = (L < NN) ? scp[L] : 0.f;
            float cR = (R < NN) ? scp[R] : 0.f;
            const float* gaG = &g_ga[g * NCAND];
            const float* gaL = (L < NN) ? &g_ga[L * NCAND] : gaG;
            const float* gaR = (R < NN) ? &g_ga[R * NCAND] : gaG;
            float g0 = ct * __ldg(&gaG[j0])     + cL * __ldg(&gaL[j0])     + cR * __ldg(&gaR[j0]);
            float g1 = ct * __ldg(&gaG[j0 + 1]) + cL * __ldg(&gaL[j0 + 1]) + cR * __ldg(&gaR[j0 + 1]);
            float g2 = ct * __ldg(&gaG[j0 + 2]) + cL * __ldg(&gaL[j0 + 2]) + cR * __ldg(&gaR[j0 + 2]);
            l0 = -100.0f * g0; l1 = -100.0f * g1; l2 = -100.0f * g2;
        }
        float m = fmaxf(l0, fmaxf(l1, l2));
        m = fmaxf(m, __shfl_xor_sync(F, m, 1));
        m = fmaxf(m, __shfl_xor_sync(F, m, 2));
        m = fmaxf(m, __shfl_xor_sync(F, m, 4));
        float e0 = act ? expf(l0 - m) : 0.f;
        float e1 = act ? expf(l1 - m) : 0.f;
        float e2 = act ? expf(l2 - m) : 0.f;
        float S = e0 + e1 + e2;
        S += __shfl_xor_sync(F, S, 1);
        S += __shfl_xor_sync(F, S, 2);
        S += __shfl_xor_sync(F, S, 4);
        float w0 = e0 / S, w1 = e1 / S, w2 = e2 / S;
        float C = ((float)j0 / 20.0f) * w0
                + ((float)(j0 + 1) / 20.0f) * w1
                + ((float)(j0 + 2) / 20.0f) * w2;
        C += __shfl_xor_sync(F, C, 1);
        C += __shfl_xor_sync(F, C, 2);
        C += __shfl_xor_sync(F, C, 4);
        if (lane == 0) sa[t] = C;
        if (lane == 8) sa[p] = C;
        __syncwarp();

        int sib = 4 * p + 3 - t;
        if (lane < 5) {
            int i = (lane == 0) ? p : (lane == 1) ? sib : (lane == 2) ? t
                  : (lane == 3) ? 2 * t + 1 : 2 * t + 2;
            if (i < NN)
                san[i] = i ? scp[i] * sa[(i - 1) >> 1] + sct[i] * sa[i] : sa[0];
        }
        __syncwarp();
        if (lane < 11) {
            int i;
            switch (lane) {
                case 0:  i = p;           break;
                case 1:  i = t;           break;
                case 2:  i = sib;         break;
                case 3:  i = 2 * t + 1;   break;
                case 4:  i = 2 * t + 2;   break;
                case 5:  i = 2 * sib + 1; break;
                case 6:  i = 2 * sib + 2; break;
                case 7:  i = 4 * t + 3;   break;
                case 8:  i = 4 * t + 4;   break;
                case 9:  i = 4 * t + 5;   break;
                default: i = 4 * t + 6;   break;
            }
            if (i < NN)
                viol[i] = i ? san[i] - san[(i - 1) >> 1] : san[0] - 1.f;
        }
        __syncwarp();
    }
    for (int i = lane; i < NN; i += 32) g_anode[i] = san[i];
}

// ================= K4: out = clip(q_node, 0, a_node), float4 =================
__global__ void k_clip(float* __restrict__ out) {
    int i4 = blockIdx.x * blockDim.x + threadIdx.x;
    if (i4 < (BATCH * NN) / 4) {
        int base = 4 * i4;
        int n0 = base % NN;
        int n1 = (n0 + 1 == NN) ? 0 : n0 + 1;
        int n2 = (n1 + 1 == NN) ? 0 : n1 + 1;
        int n3 = (n2 + 1 == NN) ? 0 : n2 + 1;
        float4 q = ((const float4*)g_qnode)[i4];
        float4 r;
        r.x = fminf(fmaxf(q.x, 0.f), __ldg(&g_anode[n0]));
        r.y = fminf(fmaxf(q.y, 0.f), __ldg(&g_anode[n1]));
        r.z = fminf(fmaxf(q.z, 0.f), __ldg(&g_anode[n2]));
        r.w = fminf(fmaxf(q.w, 0.f), __ldg(&g_anode[n3]));
        ((float4*)out)[i4] = r;
    }
}

extern "C" void kernel_launch(void* const* d_in, const int* in_sizes, int n_in,
                              void* d_out, int out_size) {
    const float* x = (const float*)d_in[0];
    const float* W = (const float*)d_in[1];
    const float* b = (const float*)d_in[2];
    float* out = (float*)d_out;

    k_gemm<<<dim3(8, 16), 256>>>(x, W, b);
    k_ga<<<NN, 128>>>();
    k_scan<<<1, 512>>>();
    k_clip<<<((BATCH * NN) / 4 + 255) / 256, 256>>>(out);
}